// round 4
// baseline (speedup 1.0000x reference)
#include <cuda_runtime.h>
#include <cuda_fp16.h>
#include <cstdint>

// ---------------- problem constants ----------------
#define NB 64          // batch
#define NSQ 16         // steps
#define NO 31          // opcodes
#define ND 1024        // hidden dim

// ---------------- GEMM tiling ----------------
#define GN 256                 // N per CTA
#define GK 64                  // halfs per stage along contraction
#define STAGES 4
#define NIT (ND / GK)          // 16 k-stages
#define GEMM_THREADS 256       // 8 warps: 2 (M) x 4 (N)

#define BBYTES (GN * 128)      // 32 KB  B tile: GN rows x 64 halfs (128B)
#define ABYTES (64 * 128)      // 8 KB   A tile: 64 rows x 64 halfs
#define STAGE_BYTES (BBYTES + ABYTES)
#define SMEM_TOTAL (STAGES * STAGE_BYTES + 1024)   // 164864 B (incl. align slack)

#define SWZ(x) ((x) ^ (((x) >> 3) & 0x70))

// ---------------- device scratch (static; allocation is forbidden) ----------------
__device__ __align__(256) __half g_Kt[(size_t)NO * ND * ND];   // [o][n][d] fp16, 62 MB
__device__ __align__(256) __half g_H[NB * ND];                 // fp16 h
__device__ __align__(256) float  g_h[NB * ND];                 // fp32 master h
__device__ __align__(256) float  g_w[NB * NO];                 // softmax weights, step t
__device__ __align__(256) float  g_P[(size_t)NO * NB * ND];    // per-opcode partials, 8 MB

// ---------------- PTX helpers (all <= sm_80 features; safe for compute_103) ----
__device__ __forceinline__ uint32_t smem_u32(const void* p) {
    uint32_t a;
    asm("{ .reg .u64 t; cvta.to.shared.u64 t, %1; cvt.u32.u64 %0, t; }" : "=r"(a) : "l"(p));
    return a;
}
__device__ __forceinline__ void cp16(uint32_t dst, const void* src) {
    asm volatile("cp.async.cg.shared.global [%0], [%1], 16;\n"
                 :: "r"(dst), "l"((unsigned long long)__cvta_generic_to_global(src)) : "memory");
}
#define CP_COMMIT() asm volatile("cp.async.commit_group;" ::: "memory")
#define CP_WAIT2()  asm volatile("cp.async.wait_group %0;" :: "n"(STAGES - 2) : "memory")

__device__ __forceinline__ void ldm_x4(uint32_t& r0, uint32_t& r1, uint32_t& r2,
                                       uint32_t& r3, uint32_t addr) {
    asm volatile("ldmatrix.sync.aligned.m8n8.x4.shared.b16 {%0,%1,%2,%3}, [%4];"
                 : "=r"(r0), "=r"(r1), "=r"(r2), "=r"(r3) : "r"(addr));
}
__device__ __forceinline__ void mma16816(float* c, uint32_t a0, uint32_t a1,
                                         uint32_t a2, uint32_t a3,
                                         uint32_t b0, uint32_t b1) {
    asm volatile(
        "mma.sync.aligned.m16n8k16.row.col.f32.f16.f16.f32 "
        "{%0,%1,%2,%3}, {%4,%5,%6,%7}, {%8,%9}, {%0,%1,%2,%3};"
        : "+f"(c[0]), "+f"(c[1]), "+f"(c[2]), "+f"(c[3])
        : "r"(a0), "r"(a1), "r"(a2), "r"(a3), "r"(b0), "r"(b1));
}

// ============================================================================
// Kernel 1: transpose + convert  K[o][d][n] fp32  ->  g_Kt[o][n][d] fp16
// grid (32, 32, 31), block (32, 8)
// ============================================================================
__global__ void ktrans_kernel(const float* __restrict__ K) {
    __shared__ float tile[32][33];
    const int o = blockIdx.z;
    const int n0 = blockIdx.x * 32;   // output-column index of K (contig in src)
    const int d0 = blockIdx.y * 32;   // contraction index (row in src)
    const int tx = threadIdx.x, ty = threadIdx.y;

    const float* src = K + ((size_t)o << 20);
#pragma unroll
    for (int i = 0; i < 4; i++) {
        int dl = ty + i * 8;
        tile[dl][tx] = src[(size_t)(d0 + dl) * ND + n0 + tx];
    }
    __syncthreads();
    __half* dst = g_Kt + ((size_t)o << 20);
#pragma unroll
    for (int i = 0; i < 4; i++) {
        int nl = ty + i * 8;
        dst[(size_t)(n0 + nl) * ND + d0 + tx] = __float2half(tile[tx][nl]);
    }
}

// ============================================================================
// Kernel 2: update / prepare.  grid (64, 4), 256 threads.  Each CTA: one batch
// row b, one 256-wide d-slice.
// t==0 : h = signal;  t>0 : h = s*sum_o P[o] + (1-s)*h, s=sigmoid(gl[t-1])
// t<16 : write g_h/g_H + softmax->g_w (y==0 block).  t==16: write d_out.
// ============================================================================
__global__ void u_kernel(const float* __restrict__ logits,
                         const float* __restrict__ operands,
                         const float* __restrict__ signal,
                         float* __restrict__ out, int t) {
    const int b = blockIdx.x;
    const int d = blockIdx.y * 256 + threadIdx.x;

    float hv;
    if (t == 0) {
        hv = signal[b * ND + d];
    } else {
        float gl = operands[(b * NSQ + (t - 1)) * 4 + 3];
        float s = 1.0f / (1.0f + expf(-gl));
        float acc = 0.0f;
#pragma unroll 1
        for (int o = 0; o < NO; o++)
            acc += g_P[((size_t)o * NB + b) * ND + d];
        hv = s * acc + (1.0f - s) * g_h[b * ND + d];
    }

    if (t < NSQ) {
        g_h[b * ND + d] = hv;
        g_H[b * ND + d] = __float2half(hv);
        if (blockIdx.y == 0 && threadIdx.x < 32) {
            const int tid = threadIdx.x;
            float l = (tid < NO) ? logits[(b * NSQ + t) * NO + tid] : -1e30f;
            float m = l;
#pragma unroll
            for (int off = 16; off; off >>= 1)
                m = fmaxf(m, __shfl_xor_sync(0xffffffff, m, off));
            float e = (tid < NO) ? expf(l - m) : 0.0f;
            float sm = e;
#pragma unroll
            for (int off = 16; off; off >>= 1)
                sm += __shfl_xor_sync(0xffffffff, sm, off);
            if (tid < NO) g_w[b * NO + tid] = e / sm;
        }
    } else {
        out[b * ND + d] = hv;
    }
}

// ============================================================================
// Kernel 3: GEMM.  grid (4 n-tiles, 31 opcodes), 256 threads, ~161 KB smem.
// P[o][b][n] = w[b,o] * sum_d H[b,d] * Kt[o][n][d]
// A row-major [64 x 1024] halfs, B "col"-major via Kt rows [n][d].
// Warp layout: wid&1 -> M-half (32 rows), wid>>1 -> N-quarter (64 cols).
// ============================================================================
__global__ void __launch_bounds__(GEMM_THREADS, 1) gemm_kernel() {
    extern __shared__ char smem_raw[];
    const uint32_t sb = (smem_u32(smem_raw) + 1023u) & ~1023u;  // 1KB-align for swizzle
    const int tid  = threadIdx.x;
    const int lane = tid & 31;
    const int wid  = tid >> 5;
    const int wm   = wid & 1;    // 0..1  M tile of 32
    const int wn   = wid >> 1;   // 0..3  N tile of 64
    const int o    = blockIdx.y;
    const int n0   = blockIdx.x * GN;

    const __half* Bsrc = g_Kt + ((size_t)o << 20) + (size_t)n0 * ND;

    // ---- producer: fill one k-stage into slot (j % STAGES) ----
    auto issue_loads = [&](int j) {
        const uint32_t base = sb + (j & (STAGES - 1)) * STAGE_BYTES;
        const uint32_t abase = base + BBYTES;
        const int kk = j * GK;   // half offset along d
#pragma unroll
        for (int i = 0; i < 8; i++) {   // B: 256 rows x 8 x16B
            int idx = tid + i * GEMM_THREADS;
            int row = idx >> 3, c = idx & 7;
            cp16(base + SWZ(row * 128 + c * 16),
                 (const char*)(Bsrc + (size_t)row * ND + kk) + c * 16);
        }
#pragma unroll
        for (int i = 0; i < 2; i++) {   // A: 64 rows x 8 x16B
            int idx = tid + i * GEMM_THREADS;
            int row = idx >> 3, c = idx & 7;
            cp16(abase + SWZ(row * 128 + c * 16),
                 (const char*)(g_H + (size_t)row * ND + kk) + c * 16);
        }
    };

    float acc[2][8][4];
#pragma unroll
    for (int mi = 0; mi < 2; mi++)
#pragma unroll
        for (int nj = 0; nj < 8; nj++)
#pragma unroll
            for (int c = 0; c < 4; c++) acc[mi][nj][c] = 0.0f;

    for (int j = 0; j < STAGES - 1; j++) { issue_loads(j); CP_COMMIT(); }

    // lane-derived ldmatrix address components
    const int a_row = (lane & 15);            // + mbase
    const int a_kb  = (lane >> 4) * 16;
    const int b_row = (lane & 7) + ((lane >> 4) << 3);  // + nbase
    const int b_kb  = ((lane >> 3) & 1) * 16;

    for (int j = 0; j < NIT; j++) {
        CP_WAIT2();
        __syncthreads();
        if (j + STAGES - 1 < NIT) issue_loads(j + STAGES - 1);
        CP_COMMIT();

        const uint32_t base  = sb + (j & (STAGES - 1)) * STAGE_BYTES;
        const uint32_t abase = base + BBYTES;
#pragma unroll
        for (int kc = 0; kc < 4; kc++) {   // 4 x k16 per stage
            uint32_t a[2][4];
#pragma unroll
            for (int mi = 0; mi < 2; mi++) {
                int row = wm * 32 + mi * 16 + a_row;
                ldm_x4(a[mi][0], a[mi][1], a[mi][2], a[mi][3],
                       abase + SWZ(row * 128 + kc * 32 + a_kb));
            }
            uint32_t bfr[4][4];
#pragma unroll
            for (int ng = 0; ng < 4; ng++) {   // 4 n16-groups per warp
                int row = wn * 64 + ng * 16 + b_row;
                ldm_x4(bfr[ng][0], bfr[ng][1], bfr[ng][2], bfr[ng][3],
                       base + SWZ(row * 128 + kc * 32 + b_kb));
            }
#pragma unroll
            for (int mi = 0; mi < 2; mi++)
#pragma unroll
                for (int nj = 0; nj < 8; nj++) {
                    const int ng = nj >> 1, hi = (nj & 1) << 1;
                    mma16816(acc[mi][nj], a[mi][0], a[mi][1], a[mi][2], a[mi][3],
                             bfr[ng][hi], bfr[ng][hi + 1]);
                }
        }
        __syncthreads();
    }

    // ---- epilogue: scale by w[b,o], write per-opcode partials ----
    const int r0  = wm * 32 + (lane >> 2);       // +mi*16, +8
    const int cb0 = wn * 64 + (lane & 3) * 2;    // +nj*8
#pragma unroll
    for (int mi = 0; mi < 2; mi++) {
        const int bA = r0 + mi * 16;
        const int bB = bA + 8;
        const float wA = g_w[bA * NO + o];
        const float wB = g_w[bB * NO + o];
        float* dA = g_P + ((size_t)o * NB + bA) * ND + n0;
        float* dB = g_P + ((size_t)o * NB + bB) * ND + n0;
#pragma unroll
        for (int nj = 0; nj < 8; nj++) {
            const int col = cb0 + nj * 8;
            float2 vA = make_float2(acc[mi][nj][0] * wA, acc[mi][nj][1] * wA);
            float2 vB = make_float2(acc[mi][nj][2] * wB, acc[mi][nj][3] * wB);
            *reinterpret_cast<float2*>(dA + col) = vA;
            *reinterpret_cast<float2*>(dB + col) = vB;
        }
    }
}

// ============================================================================
// Launch
// ============================================================================
extern "C" void kernel_launch(void* const* d_in, const int* in_sizes, int n_in,
                              void* d_out, int out_size) {
    const float* logits   = (const float*)d_in[0];  // (64,16,31)
    const float* operands = (const float*)d_in[1];  // (64,16,4)
    const float* signal   = (const float*)d_in[2];  // (64,1024)
    const float* kernels  = (const float*)d_in[3];  // (31,1024,1024)
    float* out = (float*)d_out;                     // (64,1024)

    static bool attr_set = false;
    if (!attr_set) {
        cudaFuncSetAttribute(gemm_kernel, cudaFuncAttributeMaxDynamicSharedMemorySize,
                             SMEM_TOTAL);
        attr_set = true;
    }

    ktrans_kernel<<<dim3(32, 32, NO), dim3(32, 8)>>>(kernels);
    for (int t = 0; t <= NSQ; t++) {
        u_kernel<<<dim3(NB, 4), 256>>>(logits, operands, signal, out, t);
        if (t < NSQ)
            gemm_kernel<<<dim3(4, NO), GEMM_THREADS, SMEM_TOTAL>>>();
    }
}

// round 5
// speedup vs baseline: 1.1785x; 1.1785x over previous
#include <cuda_runtime.h>
#include <cuda_fp16.h>
#include <cstdint>

// ---------------- problem constants ----------------
#define NB 64          // batch
#define NSQ 16         // steps
#define NO 31          // opcodes
#define ND 1024        // hidden dim

// ---------------- GEMM tiling ----------------
#define GN 256                 // N per CTA
#define GK 64                  // halfs per stage along contraction
#define STAGES 4
#define NIT (ND / GK)          // 16 k-stages
#define GEMM_THREADS 256       // 8 warps: 2 (M) x 4 (N)

#define BBYTES (GN * 128)      // 32 KB  B tile: GN rows x 64 halfs (128B)
#define ABYTES (64 * 128)      // 8 KB   A tile: 64 rows x 64 halfs
#define STAGE_BYTES (BBYTES + ABYTES)
#define SMEM_TOTAL (STAGES * STAGE_BYTES + 1024)   // 164864 B (incl. align slack)

#define SWZ(x) ((x) ^ (((x) >> 3) & 0x70))

// ---------------- device scratch (static; allocation is forbidden) ----------------
__device__ __align__(256) __half g_Kt[(size_t)NO * ND * ND];   // [o][n][d] fp16, 62 MB
__device__ __align__(256) __half g_H[NB * ND];                 // fp16 h
__device__ __align__(256) float  g_h[NB * ND];                 // fp32 master h
__device__ __align__(256) float  g_w[NB * NO];                 // softmax weights, step t
__device__ __align__(256) float  g_P[(size_t)NO * NB * ND];    // per-opcode partials, 8 MB

// ---------------- PTX helpers (all <= sm_80 features; safe for compute_103) ----
__device__ __forceinline__ uint32_t smem_u32(const void* p) {
    uint32_t a;
    asm("{ .reg .u64 t; cvta.to.shared.u64 t, %1; cvt.u32.u64 %0, t; }" : "=r"(a) : "l"(p));
    return a;
}
__device__ __forceinline__ void cp16(uint32_t dst, const void* src) {
    asm volatile("cp.async.cg.shared.global [%0], [%1], 16;\n"
                 :: "r"(dst), "l"((unsigned long long)__cvta_generic_to_global(src)) : "memory");
}
#define CP_COMMIT() asm volatile("cp.async.commit_group;" ::: "memory")
#define CP_WAIT2()  asm volatile("cp.async.wait_group %0;" :: "n"(STAGES - 2) : "memory")

__device__ __forceinline__ void ldm_x4(uint32_t& r0, uint32_t& r1, uint32_t& r2,
                                       uint32_t& r3, uint32_t addr) {
    asm volatile("ldmatrix.sync.aligned.m8n8.x4.shared.b16 {%0,%1,%2,%3}, [%4];"
                 : "=r"(r0), "=r"(r1), "=r"(r2), "=r"(r3) : "r"(addr));
}
__device__ __forceinline__ void mma16816(float* c, uint32_t a0, uint32_t a1,
                                         uint32_t a2, uint32_t a3,
                                         uint32_t b0, uint32_t b1) {
    asm volatile(
        "mma.sync.aligned.m16n8k16.row.col.f32.f16.f16.f32 "
        "{%0,%1,%2,%3}, {%4,%5,%6,%7}, {%8,%9}, {%0,%1,%2,%3};"
        : "+f"(c[0]), "+f"(c[1]), "+f"(c[2]), "+f"(c[3])
        : "r"(a0), "r"(a1), "r"(a2), "r"(a3), "r"(b0), "r"(b1));
}

// ============================================================================
// Kernel 1: transpose + convert  K[o][d][n] fp32  ->  g_Kt[o][n][d] fp16
// grid (32, 32, 31), block (32, 8)
// ============================================================================
__global__ void ktrans_kernel(const float* __restrict__ K) {
    __shared__ float tile[32][33];
    const int o = blockIdx.z;
    const int n0 = blockIdx.x * 32;
    const int d0 = blockIdx.y * 32;
    const int tx = threadIdx.x, ty = threadIdx.y;

    const float* src = K + ((size_t)o << 20);
#pragma unroll
    for (int i = 0; i < 4; i++) {
        int dl = ty + i * 8;
        tile[dl][tx] = src[(size_t)(d0 + dl) * ND + n0 + tx];
    }
    __syncthreads();
    __half* dst = g_Kt + ((size_t)o << 20);
#pragma unroll
    for (int i = 0; i < 4; i++) {
        int nl = ty + i * 8;
        dst[(size_t)(n0 + nl) * ND + d0 + tx] = __float2half(tile[tx][nl]);
    }
}

// ============================================================================
// Kernel 2: update / prepare.  grid (64, 2), 128 threads.
// Each thread owns one float4 slice: b = blockIdx.x, d4 = blockIdx.y*128+tid.
// t==0 : h = signal;  t>0 : h = s*sum_o P[o] + (1-s)*h, s=sigmoid(gl[t-1])
// Fully unrolled o-loop + float4 loads -> MLP~31 (R4 fix: was unroll 1 / scalar,
// latency-bound at 18.7us).
// t<16 : write g_h/g_H + softmax->g_w.  t==16: write d_out.
// ============================================================================
__global__ void u_kernel(const float* __restrict__ logits,
                         const float* __restrict__ operands,
                         const float* __restrict__ signal,
                         float* __restrict__ out, int t) {
    const int b  = blockIdx.x;
    const int d4 = blockIdx.y * 128 + threadIdx.x;   // float4 index, 0..255
    const int ND4 = ND / 4;

    float4 hv;
    if (t == 0) {
        hv = reinterpret_cast<const float4*>(signal)[b * ND4 + d4];
    } else {
        float gl = operands[(b * NSQ + (t - 1)) * 4 + 3];
        float s = 1.0f / (1.0f + expf(-gl));
        float4 acc = make_float4(0.f, 0.f, 0.f, 0.f);
        const float4* P4 = reinterpret_cast<const float4*>(g_P);
#pragma unroll
        for (int o = 0; o < NO; o++) {
            float4 p = P4[((size_t)o * NB + b) * ND4 + d4];
            acc.x += p.x; acc.y += p.y; acc.z += p.z; acc.w += p.w;
        }
        float4 ho = reinterpret_cast<const float4*>(g_h)[b * ND4 + d4];
        float is = 1.0f - s;
        hv.x = s * acc.x + is * ho.x;
        hv.y = s * acc.y + is * ho.y;
        hv.z = s * acc.z + is * ho.z;
        hv.w = s * acc.w + is * ho.w;
    }

    if (t < NSQ) {
        reinterpret_cast<float4*>(g_h)[b * ND4 + d4] = hv;
        __half2 h01 = __floats2half2_rn(hv.x, hv.y);
        __half2 h23 = __floats2half2_rn(hv.z, hv.w);
        uint2 hh;
        hh.x = *reinterpret_cast<uint32_t*>(&h01);
        hh.y = *reinterpret_cast<uint32_t*>(&h23);
        reinterpret_cast<uint2*>(g_H)[b * ND4 + d4] = hh;
        if (blockIdx.y == 0 && threadIdx.x < 32) {
            const int tid = threadIdx.x;
            float l = (tid < NO) ? logits[(b * NSQ + t) * NO + tid] : -1e30f;
            float m = l;
#pragma unroll
            for (int off = 16; off; off >>= 1)
                m = fmaxf(m, __shfl_xor_sync(0xffffffff, m, off));
            float e = (tid < NO) ? expf(l - m) : 0.0f;
            float sm = e;
#pragma unroll
            for (int off = 16; off; off >>= 1)
                sm += __shfl_xor_sync(0xffffffff, sm, off);
            if (tid < NO) g_w[b * NO + tid] = e / sm;
        }
    } else {
        reinterpret_cast<float4*>(out)[b * ND4 + d4] = hv;
    }
}

// ============================================================================
// Kernel 3: GEMM.  grid (4 n-tiles, 31 opcodes), 256 threads, ~161 KB smem.
// P[o][b][n] = w[b,o] * sum_d H[b,d] * Kt[o][n][d]
// ============================================================================
__global__ void __launch_bounds__(GEMM_THREADS, 1) gemm_kernel() {
    extern __shared__ char smem_raw[];
    const uint32_t sb = (smem_u32(smem_raw) + 1023u) & ~1023u;
    const int tid  = threadIdx.x;
    const int lane = tid & 31;
    const int wid  = tid >> 5;
    const int wm   = wid & 1;    // 0..1  M tile of 32
    const int wn   = wid >> 1;   // 0..3  N tile of 64
    const int o    = blockIdx.y;
    const int n0   = blockIdx.x * GN;

    const __half* Bsrc = g_Kt + ((size_t)o << 20) + (size_t)n0 * ND;

    auto issue_loads = [&](int j) {
        const uint32_t base = sb + (j & (STAGES - 1)) * STAGE_BYTES;
        const uint32_t abase = base + BBYTES;
        const int kk = j * GK;
#pragma unroll
        for (int i = 0; i < 8; i++) {   // B: 256 rows x 8 x16B
            int idx = tid + i * GEMM_THREADS;
            int row = idx >> 3, c = idx & 7;
            cp16(base + SWZ(row * 128 + c * 16),
                 (const char*)(Bsrc + (size_t)row * ND + kk) + c * 16);
        }
#pragma unroll
        for (int i = 0; i < 2; i++) {   // A: 64 rows x 8 x16B
            int idx = tid + i * GEMM_THREADS;
            int row = idx >> 3, c = idx & 7;
            cp16(abase + SWZ(row * 128 + c * 16),
                 (const char*)(g_H + (size_t)row * ND + kk) + c * 16);
        }
    };

    float acc[2][8][4];
#pragma unroll
    for (int mi = 0; mi < 2; mi++)
#pragma unroll
        for (int nj = 0; nj < 8; nj++)
#pragma unroll
            for (int c = 0; c < 4; c++) acc[mi][nj][c] = 0.0f;

    for (int j = 0; j < STAGES - 1; j++) { issue_loads(j); CP_COMMIT(); }

    const int a_row = (lane & 15);
    const int a_kb  = (lane >> 4) * 16;
    const int b_row = (lane & 7) + ((lane >> 4) << 3);
    const int b_kb  = ((lane >> 3) & 1) * 16;

    for (int j = 0; j < NIT; j++) {
        CP_WAIT2();
        __syncthreads();
        if (j + STAGES - 1 < NIT) issue_loads(j + STAGES - 1);
        CP_COMMIT();

        const uint32_t base  = sb + (j & (STAGES - 1)) * STAGE_BYTES;
        const uint32_t abase = base + BBYTES;
#pragma unroll
        for (int kc = 0; kc < 4; kc++) {
            uint32_t a[2][4];
#pragma unroll
            for (int mi = 0; mi < 2; mi++) {
                int row = wm * 32 + mi * 16 + a_row;
                ldm_x4(a[mi][0], a[mi][1], a[mi][2], a[mi][3],
                       abase + SWZ(row * 128 + kc * 32 + a_kb));
            }
            uint32_t bfr[4][4];
#pragma unroll
            for (int ng = 0; ng < 4; ng++) {
                int row = wn * 64 + ng * 16 + b_row;
                ldm_x4(bfr[ng][0], bfr[ng][1], bfr[ng][2], bfr[ng][3],
                       base + SWZ(row * 128 + kc * 32 + b_kb));
            }
#pragma unroll
            for (int mi = 0; mi < 2; mi++)
#pragma unroll
                for (int nj = 0; nj < 8; nj++) {
                    const int ng = nj >> 1, hi = (nj & 1) << 1;
                    mma16816(acc[mi][nj], a[mi][0], a[mi][1], a[mi][2], a[mi][3],
                             bfr[ng][hi], bfr[ng][hi + 1]);
                }
        }
        __syncthreads();
    }

    // ---- epilogue: scale by w[b,o], write per-opcode partials ----
    const int r0  = wm * 32 + (lane >> 2);
    const int cb0 = wn * 64 + (lane & 3) * 2;
#pragma unroll
    for (int mi = 0; mi < 2; mi++) {
        const int bA = r0 + mi * 16;
        const int bB = bA + 8;
        const float wA = g_w[bA * NO + o];
        const float wB = g_w[bB * NO + o];
        float* dA = g_P + ((size_t)o * NB + bA) * ND + n0;
        float* dB = g_P + ((size_t)o * NB + bB) * ND + n0;
#pragma unroll
        for (int nj = 0; nj < 8; nj++) {
            const int col = cb0 + nj * 8;
            float2 vA = make_float2(acc[mi][nj][0] * wA, acc[mi][nj][1] * wA);
            float2 vB = make_float2(acc[mi][nj][2] * wB, acc[mi][nj][3] * wB);
            *reinterpret_cast<float2*>(dA + col) = vA;
            *reinterpret_cast<float2*>(dB + col) = vB;
        }
    }
}

// ============================================================================
// Launch
// ============================================================================
extern "C" void kernel_launch(void* const* d_in, const int* in_sizes, int n_in,
                              void* d_out, int out_size) {
    const float* logits   = (const float*)d_in[0];  // (64,16,31)
    const float* operands = (const float*)d_in[1];  // (64,16,4)
    const float* signal   = (const float*)d_in[2];  // (64,1024)
    const float* kernels  = (const float*)d_in[3];  // (31,1024,1024)
    float* out = (float*)d_out;                     // (64,1024)

    static bool attr_set = false;
    if (!attr_set) {
        cudaFuncSetAttribute(gemm_kernel, cudaFuncAttributeMaxDynamicSharedMemorySize,
                             SMEM_TOTAL);
        attr_set = true;
    }

    ktrans_kernel<<<dim3(32, 32, NO), dim3(32, 8)>>>(kernels);
    for (int t = 0; t <= NSQ; t++) {
        u_kernel<<<dim3(NB, 2), 128>>>(logits, operands, signal, out, t);
        if (t < NSQ)
            gemm_kernel<<<dim3(4, NO), GEMM_THREADS, SMEM_TOTAL>>>();
    }
}

// round 7
// speedup vs baseline: 1.3176x; 1.1181x over previous
#include <cuda_runtime.h>
#include <cuda_fp16.h>
#include <cstdint>

// ---------------- problem constants ----------------
#define NB 64          // batch
#define NSQ 16         // steps
#define NO 31          // real opcodes
#define NOP 32         // padded opcode slots
#define ND 1024        // hidden dim
#define NOG 8          // opcodes per GEMM CTA
#define NGRP 4         // opcode groups (NOP/NOG)

// ---------------- GEMM tiling ----------------
#define GN 32                  // N per CTA
#define GK 64                  // halfs per stage along contraction
#define STAGES 4
#define NIT (ND / GK)          // 16 k-stages
#define GEMM_THREADS 256       // 8 warps: 2 (M) x 4 (N)

#define BBYTES (NOG * GN * 128)  // 32 KB  B: 8 ops x 32 rows x 128B
#define ABYTES (64 * 128)        // 8 KB   A: 64 rows x 128B
#define STAGE_BYTES (BBYTES + ABYTES)
#define SMEM_TOTAL (STAGES * STAGE_BYTES + 1024)   // 164864 B

#define SWZ(x) ((x) ^ (((x) >> 3) & 0x70))

// ---------------- device scratch (static; allocation is forbidden) ------------
__device__ __align__(256) __half g_Kt[(size_t)NOP * ND * ND];  // [o][n][d] fp16, 64 MB (slot 31 zero)
__device__ __align__(256) __half g_H[NB * ND];                 // fp16 h
__device__ __align__(256) float  g_h[NB * ND];                 // fp32 master h
__device__ __align__(256) float  g_w[NB * NOP];                // softmax weights (slot 31 = 0)
__device__ __align__(256) float  g_P[(size_t)NGRP * NB * ND];  // group partials, 1 MB

// ---------------- PTX helpers (<= sm_90 features; safe for compute_103) -------
__device__ __forceinline__ uint32_t smem_u32(const void* p) {
    uint32_t a;
    asm("{ .reg .u64 t; cvta.to.shared.u64 t, %1; cvt.u32.u64 %0, t; }" : "=r"(a) : "l"(p));
    return a;
}
__device__ __forceinline__ void cp16(uint32_t dst, const void* src) {
    asm volatile("cp.async.cg.shared.global [%0], [%1], 16;\n"
                 :: "r"(dst), "l"((unsigned long long)__cvta_generic_to_global(src)) : "memory");
}
#define CP_COMMIT() asm volatile("cp.async.commit_group;" ::: "memory")
#define CP_WAIT2()  asm volatile("cp.async.wait_group %0;" :: "n"(STAGES - 2) : "memory")

__device__ __forceinline__ void ldm_x4(uint32_t& r0, uint32_t& r1, uint32_t& r2,
                                       uint32_t& r3, uint32_t addr) {
    asm volatile("ldmatrix.sync.aligned.m8n8.x4.shared.b16 {%0,%1,%2,%3}, [%4];"
                 : "=r"(r0), "=r"(r1), "=r"(r2), "=r"(r3) : "r"(addr));
}
__device__ __forceinline__ void ldm_x2(uint32_t& r0, uint32_t& r1, uint32_t addr) {
    asm volatile("ldmatrix.sync.aligned.m8n8.x2.shared.b16 {%0,%1}, [%2];"
                 : "=r"(r0), "=r"(r1) : "r"(addr));
}
__device__ __forceinline__ void mma16816(float* c, uint32_t a0, uint32_t a1,
                                         uint32_t a2, uint32_t a3,
                                         uint32_t b0, uint32_t b1) {
    asm volatile(
        "mma.sync.aligned.m16n8k16.row.col.f32.f16.f16.f32 "
        "{%0,%1,%2,%3}, {%4,%5,%6,%7}, {%8,%9}, {%0,%1,%2,%3};"
        : "+f"(c[0]), "+f"(c[1]), "+f"(c[2]), "+f"(c[3])
        : "r"(a0), "r"(a1), "r"(a2), "r"(a3), "r"(b0), "r"(b1));
}

// ============================================================================
// Kernel 1: transpose + convert  K[o][d][n] fp32  ->  g_Kt[o][n][d] fp16
// grid (32, 32, 32), block (32, 8).  Slot o==31: write zeros (pad opcode).
// ============================================================================
__global__ void ktrans_kernel(const float* __restrict__ K) {
    __shared__ float tile[32][33];
    const int o = blockIdx.z;
    const int n0 = blockIdx.x * 32;
    const int d0 = blockIdx.y * 32;
    const int tx = threadIdx.x, ty = threadIdx.y;

    __half* dst = g_Kt + ((size_t)o << 20);
    if (o == NO) {  // pad slot: zero-fill
#pragma unroll
        for (int i = 0; i < 4; i++)
            dst[(size_t)(n0 + ty + i * 8) * ND + d0 + tx] = __float2half(0.0f);
        return;
    }
    const float* src = K + ((size_t)o << 20);
#pragma unroll
    for (int i = 0; i < 4; i++) {
        int dl = ty + i * 8;
        tile[dl][tx] = src[(size_t)(d0 + dl) * ND + n0 + tx];
    }
    __syncthreads();
#pragma unroll
    for (int i = 0; i < 4; i++) {
        int nl = ty + i * 8;
        dst[(size_t)(n0 + nl) * ND + d0 + tx] = __float2half(tile[tx][nl]);
    }
}

// ============================================================================
// Kernel 2: update / prepare.  grid (64, 2), 128 threads, float4 per thread.
// t==0 : h = signal;  t>0 : h = s*sum_g P[g] + (1-s)*h, s=sigmoid(gl[t-1])
// t<16 : write g_h/g_H + softmax->g_w.  t==16: write d_out.
// ============================================================================
__global__ void u_kernel(const float* __restrict__ logits,
                         const float* __restrict__ operands,
                         const float* __restrict__ signal,
                         float* __restrict__ out, int t) {
    const int b  = blockIdx.x;
    const int d4 = blockIdx.y * 128 + threadIdx.x;   // float4 index, 0..255
    const int ND4 = ND / 4;

    float4 hv;
    if (t == 0) {
        hv = reinterpret_cast<const float4*>(signal)[b * ND4 + d4];
    } else {
        float gl = operands[(b * NSQ + (t - 1)) * 4 + 3];
        float s = 1.0f / (1.0f + expf(-gl));
        float4 acc = make_float4(0.f, 0.f, 0.f, 0.f);
        const float4* P4 = reinterpret_cast<const float4*>(g_P);
#pragma unroll
        for (int g = 0; g < NGRP; g++) {
            float4 p = P4[((size_t)g * NB + b) * ND4 + d4];
            acc.x += p.x; acc.y += p.y; acc.z += p.z; acc.w += p.w;
        }
        float4 ho = reinterpret_cast<const float4*>(g_h)[b * ND4 + d4];
        float is = 1.0f - s;
        hv.x = s * acc.x + is * ho.x;
        hv.y = s * acc.y + is * ho.y;
        hv.z = s * acc.z + is * ho.z;
        hv.w = s * acc.w + is * ho.w;
    }

    if (t < NSQ) {
        reinterpret_cast<float4*>(g_h)[b * ND4 + d4] = hv;
        __half2 h01 = __floats2half2_rn(hv.x, hv.y);
        __half2 h23 = __floats2half2_rn(hv.z, hv.w);
        uint2 hh;
        hh.x = *reinterpret_cast<uint32_t*>(&h01);
        hh.y = *reinterpret_cast<uint32_t*>(&h23);
        reinterpret_cast<uint2*>(g_H)[b * ND4 + d4] = hh;
        if (blockIdx.y == 0 && threadIdx.x < 32) {
            const int tid = threadIdx.x;
            float l = (tid < NO) ? logits[(b * NSQ + t) * NO + tid] : -1e30f;
            float m = l;
#pragma unroll
            for (int off = 16; off; off >>= 1)
                m = fmaxf(m, __shfl_xor_sync(0xffffffff, m, off));
            float e = (tid < NO) ? expf(l - m) : 0.0f;
            float sm = e;
#pragma unroll
            for (int off = 16; off; off >>= 1)
                sm += __shfl_xor_sync(0xffffffff, sm, off);
            g_w[b * NOP + tid] = e / sm;   // slot 31: e=0 -> weight 0
        }
    } else {
        reinterpret_cast<float4*>(out)[b * ND4 + d4] = hv;
    }
}

// ============================================================================
// Kernel 3: GEMM.  grid (32 n-tiles, 4 op-groups), 256 threads, ~161 KB smem.
// Each CTA: 8 opcodes x (64 x 32) output, shared A tile, per-opcode register
// accumulators; epilogue folds softmax weights:
//   P[grp][b][n] = sum_{op in grp} w[b,op] * sum_d H[b,d] * Kt[op][n][d]
// Warp layout: wm = wid&1 (M 32-half), wn = wid>>1 (N 8-col slice).
// ============================================================================
__global__ void __launch_bounds__(GEMM_THREADS, 1) gemm_kernel() {
    extern __shared__ char smem_raw[];
    const uint32_t sb = (smem_u32(smem_raw) + 1023u) & ~1023u;
    const int tid  = threadIdx.x;
    const int lane = tid & 31;
    const int wid  = tid >> 5;
    const int wm   = wid & 1;    // 0..1  M tile of 32
    const int wn   = wid >> 1;   // 0..3  N tile of 8
    const int og   = blockIdx.y;             // opcode group
    const int n0   = blockIdx.x * GN;        // 0..992

    const __half* Ksrc = g_Kt + ((size_t)(og * NOG) << 20);

    // ---- producer: one k-stage (B for 8 ops + shared A) into slot j%STAGES --
    auto issue_loads = [&](int j) {
        const uint32_t base  = sb + (j & (STAGES - 1)) * STAGE_BYTES;
        const uint32_t abase = base + BBYTES;
        const int kk = j * GK;
#pragma unroll
        for (int i = 0; i < 8; i++) {   // B: 8 ops x 32 rows x 8 chunks = 2048
            int idx = tid + i * GEMM_THREADS;
            int op = idx >> 8, row = (idx >> 3) & 31, c = idx & 7;
            cp16(base + op * 4096 + SWZ(row * 128 + c * 16),
                 (const char*)(Ksrc + ((size_t)op << 20) +
                               (size_t)(n0 + row) * ND + kk) + c * 16);
        }
#pragma unroll
        for (int i = 0; i < 2; i++) {   // A: 64 rows x 8 chunks = 512
            int idx = tid + i * GEMM_THREADS;
            int row = idx >> 3, c = idx & 7;
            cp16(abase + SWZ(row * 128 + c * 16),
                 (const char*)(g_H + (size_t)row * ND + kk) + c * 16);
        }
    };

    float acc[NOG][2][4];
#pragma unroll
    for (int op = 0; op < NOG; op++)
#pragma unroll
        for (int mi = 0; mi < 2; mi++)
#pragma unroll
            for (int c = 0; c < 4; c++) acc[op][mi][c] = 0.0f;

    for (int j = 0; j < STAGES - 1; j++) { issue_loads(j); CP_COMMIT(); }

    // lane-derived ldmatrix address components
    const int a_row = (lane & 15);
    const int a_kb  = (lane >> 4) * 16;
    const int b_row = (lane & 7);
    const int b_kb  = ((lane >> 3) & 1) * 16;

    for (int j = 0; j < NIT; j++) {
        CP_WAIT2();
        __syncthreads();
        if (j + STAGES - 1 < NIT) issue_loads(j + STAGES - 1);
        CP_COMMIT();

        const uint32_t base  = sb + (j & (STAGES - 1)) * STAGE_BYTES;
        const uint32_t abase = base + BBYTES;
#pragma unroll
        for (int kc = 0; kc < 4; kc++) {   // 4 x k16 per stage
            uint32_t a[2][4];
#pragma unroll
            for (int mi = 0; mi < 2; mi++) {
                int row = wm * 32 + mi * 16 + a_row;
                ldm_x4(a[mi][0], a[mi][1], a[mi][2], a[mi][3],
                       abase + SWZ(row * 128 + kc * 32 + a_kb));
            }
#pragma unroll
            for (int op = 0; op < NOG; op++) {
                uint32_t b0, b1;
                ldm_x2(b0, b1,
                       base + op * 4096 +
                       SWZ((wn * 8 + b_row) * 128 + kc * 32 + b_kb));
                mma16816(acc[op][0], a[0][0], a[0][1], a[0][2], a[0][3], b0, b1);
                mma16816(acc[op][1], a[1][0], a[1][1], a[1][2], a[1][3], b0, b1);
            }
        }
        __syncthreads();
    }

    // ---- epilogue: fold softmax weights across the 8 ops, write group partial
    const int r_base = wm * 32 + (lane >> 2);
    const int cb0    = wn * 8 + (lane & 3) * 2;
#pragma unroll
    for (int mi = 0; mi < 2; mi++) {
        const int rA = r_base + mi * 16;
        const int rB = rA + 8;
        float2 sA = make_float2(0.f, 0.f);
        float2 sB = make_float2(0.f, 0.f);
#pragma unroll
        for (int op = 0; op < NOG; op++) {
            const float wA = g_w[rA * NOP + og * NOG + op];
            const float wB = g_w[rB * NOP + og * NOG + op];
            sA.x += wA * acc[op][mi][0];
            sA.y += wA * acc[op][mi][1];
            sB.x += wB * acc[op][mi][2];
            sB.y += wB * acc[op][mi][3];
        }
        *reinterpret_cast<float2*>(g_P + ((size_t)og * NB + rA) * ND + n0 + cb0) = sA;
        *reinterpret_cast<float2*>(g_P + ((size_t)og * NB + rB) * ND + n0 + cb0) = sB;
    }
}

// ============================================================================
// Launch
// ============================================================================
extern "C" void kernel_launch(void* const* d_in, const int* in_sizes, int n_in,
                              void* d_out, int out_size) {
    const float* logits   = (const float*)d_in[0];  // (64,16,31)
    const float* operands = (const float*)d_in[1];  // (64,16,4)
    const float* signal   = (const float*)d_in[2];  // (64,1024)
    const float* kernels  = (const float*)d_in[3];  // (31,1024,1024)
    float* out = (float*)d_out;                     // (64,1024)

    static bool attr_set = false;
    if (!attr_set) {
        cudaFuncSetAttribute(gemm_kernel, cudaFuncAttributeMaxDynamicSharedMemorySize,
                             SMEM_TOTAL);
        attr_set = true;
    }

    ktrans_kernel<<<dim3(32, 32, NOP), dim3(32, 8)>>>(kernels);
    for (int t = 0; t <= NSQ; t++) {
        u_kernel<<<dim3(NB, 2), 128>>>(logits, operands, signal, out, t);
        if (t < NSQ)
            gemm_kernel<<<dim3(32, NGRP), GEMM_THREADS, SMEM_TOTAL>>>();
    }
}